// round 3
// baseline (speedup 1.0000x reference)
#include <cuda_runtime.h>
#include <math.h>

// ElasticBand (NEB) — fused persistent kernel, prefetch-across-barrier version.
// Traffic: pos 1x read, frc 1x read, out 1x write = 460.8 MB.
// Per interior image: sums -> arrive; block0/warp0 folds+publishes coefs;
// next image's loads are issued BEFORE the barrier so DRAM stays busy during spin.

#define KMAXC 0.1f
#define DLTKC 0.02f
#define EPSC  0.1f
#define PI_F  3.14159265358979323846f

#define TF    512     // threads, fused kernel
#define KPTF  4       // float4 per thread -> 2048 per block, G = 147
#define MAX_INT 62
#define MAX_NB  1280

__device__ float g_part[(size_t)MAX_INT * MAX_NB * 6];
__device__ float g_escal[MAX_INT * 6];   // cp, cm, km, kp, mult
__device__ float g_coef[MAX_INT * 4];
__device__ unsigned int g_arrive;
__device__ unsigned int g_flag;          // #images with published coefficients

__device__ __forceinline__ float warpSum(float v) {
    #pragma unroll
    for (int o = 16; o > 0; o >>= 1) v += __shfl_xor_sync(0xffffffffu, v, o);
    return v;
}

__device__ __forceinline__ float spring_k(float ea, float eb, float emax, float eref) {
    float ei = fmaxf(ea, eb);
    float k = KMAXC - DLTKC * (emax - ei) / (emax - eref);
    if (ei < eref) k = KMAXC - DLTKC;
    return k;
}

__device__ __forceinline__ unsigned int ldAcq(const unsigned int* p) {
    unsigned int v;
    asm volatile("ld.acquire.gpu.global.u32 %0, [%1];" : "=r"(v) : "l"(p) : "memory");
    return v;
}
__device__ __forceinline__ void stRel(unsigned int* p, unsigned int v) {
    asm volatile("st.release.gpu.global.u32 [%0], %1;" :: "l"(p), "r"(v) : "memory");
}

// ---- eng-only precompute + barrier reset -----------------------------------
__global__ void nebInit(const float* __restrict__ eng, int n_img)
{
    if (threadIdx.x != 0) return;
    g_arrive = 0u;
    g_flag = 0u;

    float emin = eng[0], emax = eng[0];
    int imax = 0;
    for (int p = 1; p < n_img; p++) {
        float e = eng[p];
        if (e < emin) emin = e;
        if (e > emax) { emax = e; imax = p; }
    }
    const float eref = emin - EPSC;
    const int n_int = n_img - 2;

    for (int j = 0; j < n_int; j++) {
        const int i = j + 1;
        const float e0 = eng[i - 1], e1 = eng[i], e2 = eng[i + 1];
        const float km = spring_k(e0, e1, emax, eref);
        const float kp = spring_k(e1, e2, emax, eref);

        float cp, cm;
        if (e2 > e1 && e1 > e0)      { cp = 1.f;  cm = 0.f; }
        else if (e2 < e1 && e1 < e0) { cp = 0.f;  cm = 1.f; }
        else {
            float d1 = fabsf(e2 - e1), d0 = fabsf(e0 - e1);
            float dvmax = fmaxf(d1, d0), dvmin = fminf(d1, d0);
            if (e2 > e1)      { cp = dvmax; cm = dvmin; }
            else if (e2 < e1) { cp = dvmin; cm = dvmax; }
            else              { cp = 0.f;   cm = 0.f; }
        }
        const float mult = (j == imax) ? 2.f : 1.f;

        g_escal[j * 6 + 0] = cp;
        g_escal[j * 6 + 1] = cm;
        g_escal[j * 6 + 2] = km;
        g_escal[j * 6 + 3] = kp;
        g_escal[j * 6 + 4] = mult;
    }
}

// ---- coefficient math -------------------------------------------------------
__device__ __forceinline__ void coefFrom(
    const float* S, int ii, float& g1, float& al, float& be)
{
    const float A = S[0], B = S[1], C = S[2], D = S[3], E = S[4], W = S[5];
    const float cp = g_escal[ii * 6 + 0];
    const float cm = g_escal[ii * 6 + 1];
    const float km = g_escal[ii * 6 + 2];
    const float kp = g_escal[ii * 6 + 3];
    const float mu = g_escal[ii * 6 + 4];

    const float Stt = cp * cp * A + 2.f * cp * cm * C + cm * cm * B;
    const float Sft = cp * D + cm * E;
    const float a   = Sft / Stt;
    const float s   = (kp * sqrtf(B) - km * sqrtf(A)) / sqrtf(Stt);

    const float F   = W - Sft * Sft / Stt;
    const float Tm  = cp * C + cm * B;
    const float Tp  = cp * A + cm * C;
    const float St  = kp * Tm - km * Tp;
    const float Gv  = kp * kp * B + km * km * A - 2.f * kp * km * C
                      - 2.f * s * St + s * s * Stt;
    const float Sf  = kp * E - km * D;
    const float H   = Sf - a * St - s * Sft + s * a * Stt;

    const float sw  = (2.0f / PI_F) * atan2f(F, Gv);
    const float Hsw = H * sw;

    g1 = 1.f - Hsw;
    al = a * (Hsw - mu) * cp - km;
    be = a * (Hsw - mu) * cm + kp;
}

// ---- fused persistent kernel --------------------------------------------------
__global__ void __launch_bounds__(TF, 1) nebFused(
    const float4* __restrict__ pos4,
    const float4* __restrict__ frc4,
    float4* __restrict__ out4,
    int nvec, int n_img, int G)
{
    const int b = blockIdx.x;
    const int t = threadIdx.x;
    const int n_int = n_img - 2;

    int  idx[KPTF];
    bool ok[KPTF];
    // live state: pCur=pos[i], pA=pos[i+1], fC=frc[i], dp=pos[i]-pos[i-1]
    // prefetch:   pN=pos[i+2], fN=frc[i+1]
    float4 pCur[KPTF], pA[KPTF], fC[KPTF], dp[KPTF], pN[KPTF], fN[KPTF];

    const float4 z = make_float4(0.f, 0.f, 0.f, 0.f);

    #pragma unroll
    for (int k = 0; k < KPTF; k++) {
        int j = b * (TF * KPTF) + k * TF + t;
        idx[k] = j;
        ok[k]  = (j < nvec);
        pCur[k] = z; pA[k] = z; fC[k] = z; dp[k] = z; pN[k] = z; fN[k] = z;
        if (ok[k]) {
            float4 p0 = __ldcs(&pos4[j]);                       // pos[0]
            pCur[k]   = __ldcs(&pos4[(size_t)nvec + j]);        // pos[1]
            dp[k].x = pCur[k].x - p0.x;
            dp[k].y = pCur[k].y - p0.y;
            dp[k].z = pCur[k].z - p0.z;
            dp[k].w = pCur[k].w - p0.w;
            pA[k] = __ldcs(&pos4[(size_t)2 * nvec + j]);        // pos[2]
            fC[k] = __ldcs(&frc4[(size_t)nvec + j]);            // frc[1]
            float4 f0 = __ldcs(&frc4[j]);
            __stcs(&out4[j], f0);                               // out[0] = frc[0]
        }
    }

    __shared__ float sred[6][TF / 32];
    __shared__ float scoef[3];

    unsigned int target = 0;

    for (int ii = 0; ii < n_int; ii++) {
        const int i = ii + 1;
        const bool more = (ii + 1 < n_int);

        float4 dm[KPTF];
        float vA = 0.f, vB = 0.f, vC = 0.f, vD = 0.f, vE = 0.f, vW = 0.f;

        #pragma unroll
        for (int k = 0; k < KPTF; k++) {
            // prefetch next image FIRST so loads fly during barrier spin
            if (more && ok[k]) {
                pN[k] = __ldcs(&pos4[(size_t)(i + 2) * nvec + idx[k]]);
                fN[k] = __ldcs(&frc4[(size_t)(i + 1) * nvec + idx[k]]);
            }
            if (ok[k]) {
                dm[k].x = pA[k].x - pCur[k].x;
                dm[k].y = pA[k].y - pCur[k].y;
                dm[k].z = pA[k].z - pCur[k].z;
                dm[k].w = pA[k].w - pCur[k].w;

                vA = fmaf(dp[k].x, dp[k].x, fmaf(dp[k].y, dp[k].y, fmaf(dp[k].z, dp[k].z, fmaf(dp[k].w, dp[k].w, vA))));
                vB = fmaf(dm[k].x, dm[k].x, fmaf(dm[k].y, dm[k].y, fmaf(dm[k].z, dm[k].z, fmaf(dm[k].w, dm[k].w, vB))));
                vC = fmaf(dp[k].x, dm[k].x, fmaf(dp[k].y, dm[k].y, fmaf(dp[k].z, dm[k].z, fmaf(dp[k].w, dm[k].w, vC))));
                vD = fmaf(fC[k].x, dp[k].x, fmaf(fC[k].y, dp[k].y, fmaf(fC[k].z, dp[k].z, fmaf(fC[k].w, dp[k].w, vD))));
                vE = fmaf(fC[k].x, dm[k].x, fmaf(fC[k].y, dm[k].y, fmaf(fC[k].z, dm[k].z, fmaf(fC[k].w, dm[k].w, vE))));
                vW = fmaf(fC[k].x, fC[k].x, fmaf(fC[k].y, fC[k].y, fmaf(fC[k].z, fC[k].z, fmaf(fC[k].w, fC[k].w, vW))));
            }
        }

        // block reduce 6 sums
        float vals[6] = { vA, vB, vC, vD, vE, vW };
        #pragma unroll
        for (int c = 0; c < 6; c++) {
            float r = warpSum(vals[c]);
            if ((t & 31) == 0) sred[c][t >> 5] = r;
        }
        __syncthreads();

        target += (unsigned int)G;

        if (t == 0) {
            #pragma unroll
            for (int c = 0; c < 6; c++) {
                float s = 0.f;
                #pragma unroll
                for (int w = 0; w < TF / 32; w++) s += sred[c][w];
                g_part[((size_t)ii * G + b) * 6 + c] = s;
            }
            __threadfence();
            atomicAdd(&g_arrive, 1u);
        }

        // block 0 / warp 0: fold + publish coefficients for image ii
        if (b == 0 && t < 32) {
            while (ldAcq(&g_arrive) < target) { }
            float facc[6] = {0.f, 0.f, 0.f, 0.f, 0.f, 0.f};
            for (int p = t; p < G; p += 32) {
                const float* pp = &g_part[((size_t)ii * G + p) * 6];
                #pragma unroll
                for (int c = 0; c < 6; c++) facc[c] += pp[c];
            }
            #pragma unroll
            for (int c = 0; c < 6; c++) facc[c] = warpSum(facc[c]);
            if (t == 0) {
                float g1, al, be;
                coefFrom(facc, ii, g1, al, be);
                g_coef[ii * 4 + 0] = g1;
                g_coef[ii * 4 + 1] = al;
                g_coef[ii * 4 + 2] = be;
                __threadfence();
                stRel(&g_flag, (unsigned int)(ii + 1));
            }
        }

        // all blocks: wait for published coefficients
        if (t == 0) {
            while (ldAcq(&g_flag) < (unsigned int)(ii + 1)) { }
            scoef[0] = g_coef[ii * 4 + 0];
            scoef[1] = g_coef[ii * 4 + 1];
            scoef[2] = g_coef[ii * 4 + 2];
        }
        __syncthreads();

        const float g1 = scoef[0], al = scoef[1], be = scoef[2];

        #pragma unroll
        for (int k = 0; k < KPTF; k++) {
            if (ok[k]) {
                float4 o;
                o.x = fmaf(g1, fC[k].x, fmaf(al, dp[k].x, be * dm[k].x));
                o.y = fmaf(g1, fC[k].y, fmaf(al, dp[k].y, be * dm[k].y));
                o.z = fmaf(g1, fC[k].z, fmaf(al, dp[k].z, be * dm[k].z));
                o.w = fmaf(g1, fC[k].w, fmaf(al, dp[k].w, be * dm[k].w));
                __stcs(&out4[(size_t)i * nvec + idx[k]], o);
                // roll state
                dp[k]   = dm[k];
                pCur[k] = pA[k];
                pA[k]   = pN[k];
                fC[k]   = fN[k];
            }
        }
    }

    // out[n_img-1] = frc[n_img-1]
    #pragma unroll
    for (int k = 0; k < KPTF; k++) {
        if (ok[k]) {
            size_t g = (size_t)(n_img - 1) * nvec + idx[k];
            float4 fl = __ldcs(&frc4[g]);
            __stcs(&out4[g], fl);
        }
    }
}

// ======================= Fallback 3-kernel path ====================
#define TA  256
#define KPT 2

__global__ void __launch_bounds__(TA) nebReduce(
    const float4* __restrict__ pos4,
    const float4* __restrict__ frc4,
    int nvec, int n_img, int nb)
{
    const int b = blockIdx.x;
    const int t = threadIdx.x;

    int   idx[KPT];
    bool  ok[KPT];
    float4 pPrev[KPT], pCur[KPT];

    #pragma unroll
    for (int k = 0; k < KPT; k++) {
        int j = b * (TA * KPT) + k * TA + t;
        idx[k] = j;
        ok[k]  = (j < nvec);
        if (ok[k]) {
            pPrev[k] = pos4[j];
            pCur[k]  = pos4[(size_t)nvec + j];
        } else {
            pPrev[k] = make_float4(0.f, 0.f, 0.f, 0.f);
            pCur[k]  = make_float4(0.f, 0.f, 0.f, 0.f);
        }
    }

    __shared__ float sred[6][TA / 32];
    const int n_int = n_img - 2;

    for (int ii = 0; ii < n_int; ii++) {
        const int i = ii + 1;
        float vA = 0.f, vB = 0.f, vC = 0.f, vD = 0.f, vE = 0.f, vW = 0.f;

        #pragma unroll
        for (int k = 0; k < KPT; k++) {
            if (ok[k]) {
                float4 pNl = pos4[(size_t)(i + 1) * nvec + idx[k]];
                float4 fv  = frc4[(size_t)i * nvec + idx[k]];

                float dpx = pCur[k].x - pPrev[k].x, dmx = pNl.x - pCur[k].x;
                float dpy = pCur[k].y - pPrev[k].y, dmy = pNl.y - pCur[k].y;
                float dpz = pCur[k].z - pPrev[k].z, dmz = pNl.z - pCur[k].z;
                float dpw = pCur[k].w - pPrev[k].w, dmw = pNl.w - pCur[k].w;

                vA = fmaf(dpx, dpx, fmaf(dpy, dpy, fmaf(dpz, dpz, fmaf(dpw, dpw, vA))));
                vB = fmaf(dmx, dmx, fmaf(dmy, dmy, fmaf(dmz, dmz, fmaf(dmw, dmw, vB))));
                vC = fmaf(dpx, dmx, fmaf(dpy, dmy, fmaf(dpz, dmz, fmaf(dpw, dmw, vC))));
                vD = fmaf(fv.x, dpx, fmaf(fv.y, dpy, fmaf(fv.z, dpz, fmaf(fv.w, dpw, vD))));
                vE = fmaf(fv.x, dmx, fmaf(fv.y, dmy, fmaf(fv.z, dmz, fmaf(fv.w, dmw, vE))));
                vW = fmaf(fv.x, fv.x, fmaf(fv.y, fv.y, fmaf(fv.z, fv.z, fmaf(fv.w, fv.w, vW))));

                pPrev[k] = pCur[k];
                pCur[k]  = pNl;
            }
        }

        float vals[6] = { vA, vB, vC, vD, vE, vW };
        #pragma unroll
        for (int c = 0; c < 6; c++) {
            float r = warpSum(vals[c]);
            if ((t & 31) == 0) sred[c][t >> 5] = r;
        }
        __syncthreads();
        if (t < 6) {
            float s = 0.f;
            #pragma unroll
            for (int w = 0; w < TA / 32; w++) s += sred[t][w];
            g_part[((size_t)ii * nb + b) * 6 + t] = s;
        }
        __syncthreads();
    }
}

__global__ void nebScalars(const float* __restrict__ eng, int n_img, int nb)
{
    const int j = blockIdx.x;
    const int t = threadIdx.x;

    float acc[6] = {0.f, 0.f, 0.f, 0.f, 0.f, 0.f};
    for (int b = t; b < nb; b += blockDim.x) {
        #pragma unroll
        for (int c = 0; c < 6; c++)
            acc[c] += g_part[((size_t)j * nb + b) * 6 + c];
    }

    __shared__ float sred[6][8];
    #pragma unroll
    for (int c = 0; c < 6; c++) {
        float r = warpSum(acc[c]);
        if ((t & 31) == 0) sred[c][t >> 5] = r;
    }
    __syncthreads();

    if (t == 0) {
        float S[6];
        #pragma unroll
        for (int c = 0; c < 6; c++) {
            float s = 0.f;
            #pragma unroll
            for (int w = 0; w < 8; w++) s += sred[c][w];
            S[c] = s;
        }
        float g1, al, be;
        coefFrom(S, j, g1, al, be);
        g_coef[j * 4 + 0] = g1;
        g_coef[j * 4 + 1] = al;
        g_coef[j * 4 + 2] = be;
    }
}

__global__ void nebOut(
    const float4* __restrict__ pos4,
    const float4* __restrict__ frc4,
    float4* __restrict__ out4,
    int nvec, int n_img)
{
    size_t gid = (size_t)blockIdx.x * blockDim.x + threadIdx.x;
    size_t total = (size_t)n_img * nvec;
    if (gid >= total) return;

    int img = (int)(gid / (unsigned)nvec);
    float4 f = frc4[gid];

    if (img == 0 || img == n_img - 1) { out4[gid] = f; return; }

    const int ii = img - 1;
    const float g1 = __ldg(&g_coef[ii * 4 + 0]);
    const float al = __ldg(&g_coef[ii * 4 + 1]);
    const float be = __ldg(&g_coef[ii * 4 + 2]);

    float4 pm = pos4[gid - nvec];
    float4 pc = pos4[gid];
    float4 pp = pos4[gid + nvec];

    float4 o;
    o.x = fmaf(g1, f.x, fmaf(al, pc.x - pm.x, be * (pp.x - pc.x)));
    o.y = fmaf(g1, f.y, fmaf(al, pc.y - pm.y, be * (pp.y - pc.y)));
    o.z = fmaf(g1, f.z, fmaf(al, pc.z - pm.z, be * (pp.z - pc.z)));
    o.w = fmaf(g1, f.w, fmaf(al, pc.w - pm.w, be * (pp.w - pc.w)));
    out4[gid] = o;
}

// =============================================================================
extern "C" void kernel_launch(void* const* d_in, const int* in_sizes, int n_in,
                              void* d_out, int out_size)
{
    const float* pos = (const float*)d_in[0];
    const float* frc = (const float*)d_in[1];
    const float* eng = (const float*)d_in[2];

    const int n_img    = in_sizes[2];
    const long per_img = (long)in_sizes[0] / n_img;
    const int  nvec    = (int)(per_img / 4);
    const int  n_int   = n_img - 2;

    const float4* pos4 = (const float4*)pos;
    const float4* frc4 = (const float4*)frc;
    float4* out4 = (float4*)d_out;

    const int G = (nvec + TF * KPTF - 1) / (TF * KPTF);

    int dev = 0;
    cudaGetDevice(&dev);
    int numSM = 0;
    cudaDeviceGetAttribute(&numSM, cudaDevAttrMultiProcessorCount, dev);
    int maxB = 0;
    cudaOccupancyMaxActiveBlocksPerMultiprocessor(&maxB, nebFused, TF, 0);

    if (n_img >= 3 && n_int <= MAX_INT && G <= MAX_NB &&
        (long)maxB * numSM >= G) {
        nebInit<<<1, 32>>>(eng, n_img);
        nebFused<<<G, TF>>>(pos4, frc4, out4, nvec, n_img, G);
    } else {
        const int nb = (nvec + TA * KPT - 1) / (TA * KPT);
        nebReduce<<<nb, TA>>>(pos4, frc4, nvec, n_img, nb);
        nebScalars<<<n_int, 256>>>(eng, n_img, nb);
        size_t total = (size_t)n_img * nvec;
        int blocksC = (int)((total + 255) / 256);
        nebOut<<<blocksC, 256>>>(pos4, frc4, out4, nvec, n_img);
    }
}

// round 4
// speedup vs baseline: 1.4380x; 1.4380x over previous
#include <cuda_runtime.h>
#include <math.h>
#include <stdint.h>

// ElasticBand (NEB) — fused persistent kernel, cp.async smem-pipeline version.
// Traffic: pos 1x read, frc 1x read, out 1x write = 460.8 MB.
// cp.async prefetch of image i+1 is committed BEFORE the grid barrier for image i,
// so DRAM stays busy during the barrier spin. Register state is tiny (no spill).

#define KMAXC 0.1f
#define DLTKC 0.02f
#define EPSC  0.1f
#define PI_F  3.14159265358979323846f

#define TF      1024            // threads, fused kernel
#define KPTF    2               // float4 per thread
#define TILE    (TF * KPTF)     // 2048 float4 per block
#define TILE_B  (TILE * 16)     // 32768 bytes per tile buffer
#define MAX_INT 62
#define MAX_G   256
#define MAX_NB  1280

__device__ float g_part[(size_t)MAX_INT * MAX_NB * 6];
__device__ float g_escal[MAX_INT * 6];   // cp, cm, km, kp, mult
__device__ float g_coef[MAX_INT * 4];
__device__ unsigned int g_arrive;
__device__ unsigned int g_flag;

__device__ __forceinline__ float warpSum(float v) {
    #pragma unroll
    for (int o = 16; o > 0; o >>= 1) v += __shfl_xor_sync(0xffffffffu, v, o);
    return v;
}

__device__ __forceinline__ float spring_k(float ea, float eb, float emax, float eref) {
    float ei = fmaxf(ea, eb);
    float k = KMAXC - DLTKC * (emax - ei) / (emax - eref);
    if (ei < eref) k = KMAXC - DLTKC;
    return k;
}

__device__ __forceinline__ unsigned int ldAcq(const unsigned int* p) {
    unsigned int v;
    asm volatile("ld.acquire.gpu.global.u32 %0, [%1];" : "=r"(v) : "l"(p) : "memory");
    return v;
}
__device__ __forceinline__ void stRel(unsigned int* p, unsigned int v) {
    asm volatile("st.release.gpu.global.u32 [%0], %1;" :: "l"(p), "r"(v) : "memory");
}

__device__ __forceinline__ void cpAsync16(uint32_t dst, const float4* src, bool p) {
    asm volatile(
        "{\n\t.reg .pred q;\n\t"
        "setp.ne.u32 q, %2, 0;\n\t"
        "@q cp.async.cg.shared.global [%0], [%1], 16;\n\t}"
        :: "r"(dst), "l"(src), "r"((int)p) : "memory");
}
#define CP_COMMIT() asm volatile("cp.async.commit_group;" ::: "memory")
#define CP_WAIT1()  asm volatile("cp.async.wait_group 1;" ::: "memory")

__device__ __forceinline__ uint32_t smemU32(const void* p) {
    uint32_t a;
    asm("{ .reg .u64 u; cvta.to.shared.u64 u, %1; cvt.u32.u64 %0, u; }"
        : "=r"(a) : "l"(p));
    return a;
}

// ---- eng-only precompute + barrier reset -----------------------------------
__global__ void nebInit(const float* __restrict__ eng, int n_img)
{
    if (threadIdx.x != 0) return;
    g_arrive = 0u;
    g_flag = 0u;

    float emin = eng[0], emax = eng[0];
    int imax = 0;
    for (int p = 1; p < n_img; p++) {
        float e = eng[p];
        if (e < emin) emin = e;
        if (e > emax) { emax = e; imax = p; }
    }
    const float eref = emin - EPSC;
    const int n_int = n_img - 2;

    for (int j = 0; j < n_int; j++) {
        const int i = j + 1;
        const float e0 = eng[i - 1], e1 = eng[i], e2 = eng[i + 1];
        const float km = spring_k(e0, e1, emax, eref);
        const float kp = spring_k(e1, e2, emax, eref);

        float cp, cm;
        if (e2 > e1 && e1 > e0)      { cp = 1.f;  cm = 0.f; }
        else if (e2 < e1 && e1 < e0) { cp = 0.f;  cm = 1.f; }
        else {
            float d1 = fabsf(e2 - e1), d0 = fabsf(e0 - e1);
            float dvmax = fmaxf(d1, d0), dvmin = fminf(d1, d0);
            if (e2 > e1)      { cp = dvmax; cm = dvmin; }
            else if (e2 < e1) { cp = dvmin; cm = dvmax; }
            else              { cp = 0.f;   cm = 0.f; }
        }
        const float mult = (j == imax) ? 2.f : 1.f;

        g_escal[j * 6 + 0] = cp;
        g_escal[j * 6 + 1] = cm;
        g_escal[j * 6 + 2] = km;
        g_escal[j * 6 + 3] = kp;
        g_escal[j * 6 + 4] = mult;
    }
}

// ---- coefficient math -------------------------------------------------------
__device__ __forceinline__ void coefFrom(
    const float* S, int ii, float& g1, float& al, float& be)
{
    const float A = S[0], B = S[1], C = S[2], D = S[3], E = S[4], W = S[5];
    const float cp = g_escal[ii * 6 + 0];
    const float cm = g_escal[ii * 6 + 1];
    const float km = g_escal[ii * 6 + 2];
    const float kp = g_escal[ii * 6 + 3];
    const float mu = g_escal[ii * 6 + 4];

    const float Stt = cp * cp * A + 2.f * cp * cm * C + cm * cm * B;
    const float Sft = cp * D + cm * E;
    const float a   = Sft / Stt;
    const float s   = (kp * sqrtf(B) - km * sqrtf(A)) / sqrtf(Stt);

    const float F   = W - Sft * Sft / Stt;
    const float Tm  = cp * C + cm * B;
    const float Tp  = cp * A + cm * C;
    const float St  = kp * Tm - km * Tp;
    const float Gv  = kp * kp * B + km * km * A - 2.f * kp * km * C
                      - 2.f * s * St + s * s * Stt;
    const float Sf  = kp * E - km * D;
    const float H   = Sf - a * St - s * Sft + s * a * Stt;

    const float sw  = (2.0f / PI_F) * atan2f(F, Gv);
    const float Hsw = H * sw;

    g1 = 1.f - Hsw;
    al = a * (Hsw - mu) * cp - km;
    be = a * (Hsw - mu) * cm + kp;
}

// ---- fused persistent kernel: cp.async smem pipeline ------------------------
// smem layout: posRing[3][TILE] | frcRing[2][TILE] | sred[6*32] | scoef[4]
__global__ void __launch_bounds__(TF, 1) nebFused(
    const float4* __restrict__ pos4,
    const float4* __restrict__ frc4,
    float4* __restrict__ out4,
    int nvec, int n_img, int G)
{
    extern __shared__ char smem[];
    float* sred  = (float*)(smem + 5 * TILE_B);
    float* scoef = sred + 6 * 32;
    const uint32_t sbase = smemU32(smem);

    const int b = blockIdx.x;
    const int t = threadIdx.x;
    const int wid = t >> 5;
    const int lane = t & 31;
    const int n_int = n_img - 2;

    int  idx[KPTF];
    bool ok[KPTF];
    uint32_t slot[KPTF];  // byte offset within a tile buffer
    #pragma unroll
    for (int k = 0; k < KPTF; k++) {
        idx[k]  = b * TILE + k * TF + t;
        ok[k]   = (idx[k] < nvec);
        slot[k] = (uint32_t)(k * TF + t) * 16u;
    }

    // --- prologue: group G1 = pos0->buf0, pos1->buf1 ; G2 = pos2->buf2, frc1->fbuf1
    #pragma unroll
    for (int k = 0; k < KPTF; k++)
        cpAsync16(sbase + 0 * TILE_B + slot[k], pos4 + idx[k], ok[k]);
    #pragma unroll
    for (int k = 0; k < KPTF; k++)
        cpAsync16(sbase + 1 * TILE_B + slot[k], pos4 + (size_t)nvec + idx[k], ok[k]);
    CP_COMMIT();
    #pragma unroll
    for (int k = 0; k < KPTF; k++)
        cpAsync16(sbase + 2 * TILE_B + slot[k], pos4 + (size_t)2 * nvec + idx[k], ok[k]);
    #pragma unroll
    for (int k = 0; k < KPTF; k++)
        cpAsync16(sbase + (3 + 1) * TILE_B + slot[k], frc4 + (size_t)nvec + idx[k], ok[k]);
    CP_COMMIT();

    // out[0] = frc[0] (direct, bypass smem)
    #pragma unroll
    for (int k = 0; k < KPTF; k++) {
        if (ok[k]) {
            float4 f0 = __ldcs(&frc4[idx[k]]);
            __stcs(&out4[idx[k]], f0);
        }
    }

    CP_WAIT1();  // G1 done: pos0, pos1 resident
    float4 dp[KPTF];
    #pragma unroll
    for (int k = 0; k < KPTF; k++) {
        float4 p0 = *(const float4*)(smem + 0 * TILE_B + slot[k]);
        float4 p1 = *(const float4*)(smem + 1 * TILE_B + slot[k]);
        dp[k].x = p1.x - p0.x; dp[k].y = p1.y - p0.y;
        dp[k].z = p1.z - p0.z; dp[k].w = p1.w - p0.w;
    }

    unsigned int target = 0;

    for (int ii = 0; ii < n_int; ii++) {
        const int i = ii + 1;
        const bool more = (ii + 1 < n_int);

        // prefetch for image i+1: pos[i+2] -> buf (i+2)%3, frc[i+1] -> fbuf (i+1)&1
        if (more) {
            const int pb = (i + 2) % 3;
            const int fb = (i + 1) & 1;
            #pragma unroll
            for (int k = 0; k < KPTF; k++)
                cpAsync16(sbase + pb * TILE_B + slot[k],
                          pos4 + (size_t)(i + 2) * nvec + idx[k], ok[k]);
            #pragma unroll
            for (int k = 0; k < KPTF; k++)
                cpAsync16(sbase + (3 + fb) * TILE_B + slot[k],
                          frc4 + (size_t)(i + 1) * nvec + idx[k], ok[k]);
        }
        CP_COMMIT();
        CP_WAIT1();  // all but the just-committed group done -> pos[i+1], frc[i] ready

        const int bi  = i % 3;        // pos[i]
        const int bi1 = (i + 1) % 3;  // pos[i+1]
        const int fbi = i & 1;        // frc[i]

        float4 dm[KPTF], fC[KPTF];
        float vA = 0.f, vB = 0.f, vC = 0.f, vD = 0.f, vE = 0.f, vW = 0.f;

        #pragma unroll
        for (int k = 0; k < KPTF; k++) {
            if (ok[k]) {
                float4 pa = *(const float4*)(smem + bi  * TILE_B + slot[k]);
                float4 pb = *(const float4*)(smem + bi1 * TILE_B + slot[k]);
                fC[k]     = *(const float4*)(smem + (3 + fbi) * TILE_B + slot[k]);
                dm[k].x = pb.x - pa.x; dm[k].y = pb.y - pa.y;
                dm[k].z = pb.z - pa.z; dm[k].w = pb.w - pa.w;

                vA = fmaf(dp[k].x, dp[k].x, fmaf(dp[k].y, dp[k].y, fmaf(dp[k].z, dp[k].z, fmaf(dp[k].w, dp[k].w, vA))));
                vB = fmaf(dm[k].x, dm[k].x, fmaf(dm[k].y, dm[k].y, fmaf(dm[k].z, dm[k].z, fmaf(dm[k].w, dm[k].w, vB))));
                vC = fmaf(dp[k].x, dm[k].x, fmaf(dp[k].y, dm[k].y, fmaf(dp[k].z, dm[k].z, fmaf(dp[k].w, dm[k].w, vC))));
                vD = fmaf(fC[k].x, dp[k].x, fmaf(fC[k].y, dp[k].y, fmaf(fC[k].z, dp[k].z, fmaf(fC[k].w, dp[k].w, vD))));
                vE = fmaf(fC[k].x, dm[k].x, fmaf(fC[k].y, dm[k].y, fmaf(fC[k].z, dm[k].z, fmaf(fC[k].w, dm[k].w, vE))));
                vW = fmaf(fC[k].x, fC[k].x, fmaf(fC[k].y, fC[k].y, fmaf(fC[k].z, fC[k].z, fmaf(fC[k].w, fC[k].w, vW))));
            } else {
                dm[k] = make_float4(0.f, 0.f, 0.f, 0.f);
                fC[k] = make_float4(0.f, 0.f, 0.f, 0.f);
            }
        }

        // stage 1: per-warp reduce -> sred[c*32 + wid]
        {
            float vals[6] = { vA, vB, vC, vD, vE, vW };
            #pragma unroll
            for (int c = 0; c < 6; c++) {
                float r = warpSum(vals[c]);
                if (lane == 0) sred[c * 32 + wid] = r;
            }
        }
        __syncthreads();

        target += (unsigned int)G;

        // stage 2 + barrier handled by warp 0
        if (t < 32) {
            float facc[6];
            #pragma unroll
            for (int c = 0; c < 6; c++) facc[c] = warpSum(sred[c * 32 + t]);

            if (t == 0) {
                float* pp = &g_part[((size_t)ii * G + b) * 6];
                #pragma unroll
                for (int c = 0; c < 6; c++) pp[c] = facc[c];
                __threadfence();
                atomicAdd(&g_arrive, 1u);
            }

            if (b == 0) {
                if (t == 0) {
                    while (ldAcq(&g_arrive) < target) { }
                }
                __syncwarp();
                float s6[6] = {0.f, 0.f, 0.f, 0.f, 0.f, 0.f};
                for (int p = t; p < G; p += 32) {
                    const float* pp = &g_part[((size_t)ii * G + p) * 6];
                    #pragma unroll
                    for (int c = 0; c < 6; c++) s6[c] += pp[c];
                }
                #pragma unroll
                for (int c = 0; c < 6; c++) s6[c] = warpSum(s6[c]);
                if (t == 0) {
                    float g1, al, be;
                    coefFrom(s6, ii, g1, al, be);
                    g_coef[ii * 4 + 0] = g1;
                    g_coef[ii * 4 + 1] = al;
                    g_coef[ii * 4 + 2] = be;
                    __threadfence();
                    stRel(&g_flag, (unsigned int)(ii + 1));
                }
            }

            if (t == 0) {
                while (ldAcq(&g_flag) < (unsigned int)(ii + 1)) { }
                scoef[0] = g_coef[ii * 4 + 0];
                scoef[1] = g_coef[ii * 4 + 1];
                scoef[2] = g_coef[ii * 4 + 2];
            }
        }
        __syncthreads();

        const float g1 = scoef[0], al = scoef[1], be = scoef[2];

        #pragma unroll
        for (int k = 0; k < KPTF; k++) {
            if (ok[k]) {
                float4 o;
                o.x = fmaf(g1, fC[k].x, fmaf(al, dp[k].x, be * dm[k].x));
                o.y = fmaf(g1, fC[k].y, fmaf(al, dp[k].y, be * dm[k].y));
                o.z = fmaf(g1, fC[k].z, fmaf(al, dp[k].z, be * dm[k].z));
                o.w = fmaf(g1, fC[k].w, fmaf(al, dp[k].w, be * dm[k].w));
                __stcs(&out4[(size_t)i * nvec + idx[k]], o);
            }
            dp[k] = dm[k];
        }
    }

    // out[n_img-1] = frc[n_img-1]
    #pragma unroll
    for (int k = 0; k < KPTF; k++) {
        if (ok[k]) {
            size_t g = (size_t)(n_img - 1) * nvec + idx[k];
            float4 fl = __ldcs(&frc4[g]);
            __stcs(&out4[g], fl);
        }
    }
}

// ======================= Fallback 3-kernel path (proven 141.6us) =============
#define TA  256
#define KPT 2

__global__ void __launch_bounds__(TA) nebReduce(
    const float4* __restrict__ pos4,
    const float4* __restrict__ frc4,
    int nvec, int n_img, int nb)
{
    const int b = blockIdx.x;
    const int t = threadIdx.x;

    int   idx[KPT];
    bool  ok[KPT];
    float4 pPrev[KPT], pCur[KPT];

    #pragma unroll
    for (int k = 0; k < KPT; k++) {
        int j = b * (TA * KPT) + k * TA + t;
        idx[k] = j;
        ok[k]  = (j < nvec);
        if (ok[k]) {
            pPrev[k] = pos4[j];
            pCur[k]  = pos4[(size_t)nvec + j];
        } else {
            pPrev[k] = make_float4(0.f, 0.f, 0.f, 0.f);
            pCur[k]  = make_float4(0.f, 0.f, 0.f, 0.f);
        }
    }

    __shared__ float sred[6][TA / 32];
    const int n_int = n_img - 2;

    for (int ii = 0; ii < n_int; ii++) {
        const int i = ii + 1;
        float vA = 0.f, vB = 0.f, vC = 0.f, vD = 0.f, vE = 0.f, vW = 0.f;

        #pragma unroll
        for (int k = 0; k < KPT; k++) {
            if (ok[k]) {
                float4 pNl = pos4[(size_t)(i + 1) * nvec + idx[k]];
                float4 fv  = frc4[(size_t)i * nvec + idx[k]];

                float dpx = pCur[k].x - pPrev[k].x, dmx = pNl.x - pCur[k].x;
                float dpy = pCur[k].y - pPrev[k].y, dmy = pNl.y - pCur[k].y;
                float dpz = pCur[k].z - pPrev[k].z, dmz = pNl.z - pCur[k].z;
                float dpw = pCur[k].w - pPrev[k].w, dmw = pNl.w - pCur[k].w;

                vA = fmaf(dpx, dpx, fmaf(dpy, dpy, fmaf(dpz, dpz, fmaf(dpw, dpw, vA))));
                vB = fmaf(dmx, dmx, fmaf(dmy, dmy, fmaf(dmz, dmz, fmaf(dmw, dmw, vB))));
                vC = fmaf(dpx, dmx, fmaf(dpy, dmy, fmaf(dpz, dmz, fmaf(dpw, dmw, vC))));
                vD = fmaf(fv.x, dpx, fmaf(fv.y, dpy, fmaf(fv.z, dpz, fmaf(fv.w, dpw, vD))));
                vE = fmaf(fv.x, dmx, fmaf(fv.y, dmy, fmaf(fv.z, dmz, fmaf(fv.w, dmw, vE))));
                vW = fmaf(fv.x, fv.x, fmaf(fv.y, fv.y, fmaf(fv.z, fv.z, fmaf(fv.w, fv.w, vW))));

                pPrev[k] = pCur[k];
                pCur[k]  = pNl;
            }
        }

        float vals[6] = { vA, vB, vC, vD, vE, vW };
        #pragma unroll
        for (int c = 0; c < 6; c++) {
            float r = warpSum(vals[c]);
            if ((t & 31) == 0) sred[c][t >> 5] = r;
        }
        __syncthreads();
        if (t < 6) {
            float s = 0.f;
            #pragma unroll
            for (int w = 0; w < TA / 32; w++) s += sred[t][w];
            g_part[((size_t)ii * nb + b) * 6 + t] = s;
        }
        __syncthreads();
    }
}

__global__ void nebScalars(const float* __restrict__ eng, int n_img, int nb)
{
    const int j = blockIdx.x;
    const int t = threadIdx.x;

    float acc[6] = {0.f, 0.f, 0.f, 0.f, 0.f, 0.f};
    for (int b = t; b < nb; b += blockDim.x) {
        #pragma unroll
        for (int c = 0; c < 6; c++)
            acc[c] += g_part[((size_t)j * nb + b) * 6 + c];
    }

    __shared__ float sred[6][8];
    #pragma unroll
    for (int c = 0; c < 6; c++) {
        float r = warpSum(acc[c]);
        if ((t & 31) == 0) sred[c][t >> 5] = r;
    }
    __syncthreads();

    if (t == 0) {
        float S[6];
        #pragma unroll
        for (int c = 0; c < 6; c++) {
            float s = 0.f;
            #pragma unroll
            for (int w = 0; w < 8; w++) s += sred[c][w];
            S[c] = s;
        }
        float g1, al, be;
        coefFrom(S, j, g1, al, be);
        g_coef[j * 4 + 0] = g1;
        g_coef[j * 4 + 1] = al;
        g_coef[j * 4 + 2] = be;
    }
}

__global__ void nebOut(
    const float4* __restrict__ pos4,
    const float4* __restrict__ frc4,
    float4* __restrict__ out4,
    int nvec, int n_img)
{
    size_t gid = (size_t)blockIdx.x * blockDim.x + threadIdx.x;
    size_t total = (size_t)n_img * nvec;
    if (gid >= total) return;

    int img = (int)(gid / (unsigned)nvec);
    float4 f = frc4[gid];

    if (img == 0 || img == n_img - 1) { out4[gid] = f; return; }

    const int ii = img - 1;
    const float g1 = __ldg(&g_coef[ii * 4 + 0]);
    const float al = __ldg(&g_coef[ii * 4 + 1]);
    const float be = __ldg(&g_coef[ii * 4 + 2]);

    float4 pm = pos4[gid - nvec];
    float4 pc = pos4[gid];
    float4 pp = pos4[gid + nvec];

    float4 o;
    o.x = fmaf(g1, f.x, fmaf(al, pc.x - pm.x, be * (pp.x - pc.x)));
    o.y = fmaf(g1, f.y, fmaf(al, pc.y - pm.y, be * (pp.y - pc.y)));
    o.z = fmaf(g1, f.z, fmaf(al, pc.z - pm.z, be * (pp.z - pc.z)));
    o.w = fmaf(g1, f.w, fmaf(al, pc.w - pm.w, be * (pp.w - pc.w)));
    out4[gid] = o;
}

// =============================================================================
extern "C" void kernel_launch(void* const* d_in, const int* in_sizes, int n_in,
                              void* d_out, int out_size)
{
    const float* pos = (const float*)d_in[0];
    const float* frc = (const float*)d_in[1];
    const float* eng = (const float*)d_in[2];

    const int n_img    = in_sizes[2];
    const long per_img = (long)in_sizes[0] / n_img;
    const int  nvec    = (int)(per_img / 4);
    const int  n_int   = n_img - 2;

    const float4* pos4 = (const float4*)pos;
    const float4* frc4 = (const float4*)frc;
    float4* out4 = (float4*)d_out;

    const int G = (nvec + TILE - 1) / TILE;
    const size_t shbytes = 5 * (size_t)TILE_B + (6 * 32 + 8) * sizeof(float);

    int dev = 0;
    cudaGetDevice(&dev);
    int numSM = 0;
    cudaDeviceGetAttribute(&numSM, cudaDevAttrMultiProcessorCount, dev);

    bool fusedOK = false;
    if (n_img >= 3 && n_int <= MAX_INT && G <= MAX_G) {
        cudaError_t e = cudaFuncSetAttribute(
            nebFused, cudaFuncAttributeMaxDynamicSharedMemorySize, (int)shbytes);
        if (e == cudaSuccess) {
            int maxB = 0;
            cudaOccupancyMaxActiveBlocksPerMultiprocessor(&maxB, nebFused, TF, shbytes);
            if ((long)maxB * numSM >= G) fusedOK = true;
        }
    }

    if (fusedOK) {
        nebInit<<<1, 32>>>(eng, n_img);
        nebFused<<<G, TF, shbytes>>>(pos4, frc4, out4, nvec, n_img, G);
    } else {
        const int nb = (nvec + TA * KPT - 1) / (TA * KPT);
        nebReduce<<<nb, TA>>>(pos4, frc4, nvec, n_img, nb);
        nebScalars<<<n_int, 256>>>(eng, n_img, nb);
        size_t total = (size_t)n_img * nvec;
        int blocksC = (int)((total + 255) / 256);
        nebOut<<<blocksC, 256>>>(pos4, frc4, out4, nvec, n_img);
    }
}

// round 5
// speedup vs baseline: 1.8046x; 1.2550x over previous
#include <cuda_runtime.h>
#include <math.h>

// ElasticBand (NEB) — chunked L2-pipelined 3-phase scheme.
// Interior images are processed in chunks that fit in L2 (~8 images = 77MB).
// Per chunk: R (rolling reduce, fills L2) -> S (fold partials -> coefs)
//            -> O (rolling output, reads pos/frc as L2 hits, streams out).
// No grid barriers, no persistence: plain default-stream launches.

#define KMAXC 0.1f
#define DLTKC 0.02f
#define EPSC  0.1f
#define PI_F  3.14159265358979323846f

#define TA   256                 // threads per block (R and O)
#define KPT  2                   // float4 per thread
#define TILEA (TA * KPT)         // 512 float4 per block
#define NW   (TA / 32)           // warps per block
#define MAX_INT 62
#define MAX_NB  1280
#define CHUNK   8                // interior images per chunk

// per-(image,block,warp) partials: [ii][block][warp][6]
__device__ float g_part[(size_t)MAX_INT * MAX_NB * NW * 6];
__device__ float g_escal[MAX_INT * 6];   // cp, cm, km, kp, mult
__device__ float g_coef[MAX_INT * 4];    // g1, alpha, beta

__device__ __forceinline__ float warpSum(float v) {
    #pragma unroll
    for (int o = 16; o > 0; o >>= 1) v += __shfl_xor_sync(0xffffffffu, v, o);
    return v;
}

__device__ __forceinline__ float spring_k(float ea, float eb, float emax, float eref) {
    float ei = fmaxf(ea, eb);
    float k = KMAXC - DLTKC * (emax - ei) / (emax - eref);
    if (ei < eref) k = KMAXC - DLTKC;
    return k;
}

// ---- eng-only precompute (1 tiny block) -------------------------------------
__global__ void nebInit(const float* __restrict__ eng, int n_img)
{
    if (threadIdx.x != 0) return;

    float emin = eng[0], emax = eng[0];
    int imax = 0;
    for (int p = 1; p < n_img; p++) {
        float e = eng[p];
        if (e < emin) emin = e;
        if (e > emax) { emax = e; imax = p; }   // strict > keeps first max
    }
    const float eref = emin - EPSC;
    const int n_int = n_img - 2;

    for (int j = 0; j < n_int; j++) {
        const int i = j + 1;
        const float e0 = eng[i - 1], e1 = eng[i], e2 = eng[i + 1];
        const float km = spring_k(e0, e1, emax, eref);
        const float kp = spring_k(e1, e2, emax, eref);

        float cp, cm;
        if (e2 > e1 && e1 > e0)      { cp = 1.f;  cm = 0.f; }
        else if (e2 < e1 && e1 < e0) { cp = 0.f;  cm = 1.f; }
        else {
            float d1 = fabsf(e2 - e1), d0 = fabsf(e0 - e1);
            float dvmax = fmaxf(d1, d0), dvmin = fminf(d1, d0);
            if (e2 > e1)      { cp = dvmax; cm = dvmin; }
            else if (e2 < e1) { cp = dvmin; cm = dvmax; }
            else              { cp = 0.f;   cm = 0.f; }
        }
        const float mult = (j == imax) ? 2.f : 1.f;  // .at[i_raw] quirk

        g_escal[j * 6 + 0] = cp;
        g_escal[j * 6 + 1] = cm;
        g_escal[j * 6 + 2] = km;
        g_escal[j * 6 + 3] = kp;
        g_escal[j * 6 + 4] = mult;
    }
}

// ---- coefficient math --------------------------------------------------------
__device__ __forceinline__ void coefFrom(
    const float* S, int ii, float& g1, float& al, float& be)
{
    const float A = S[0], B = S[1], C = S[2], D = S[3], E = S[4], W = S[5];
    const float cp = g_escal[ii * 6 + 0];
    const float cm = g_escal[ii * 6 + 1];
    const float km = g_escal[ii * 6 + 2];
    const float kp = g_escal[ii * 6 + 3];
    const float mu = g_escal[ii * 6 + 4];

    const float Stt = cp * cp * A + 2.f * cp * cm * C + cm * cm * B;
    const float Sft = cp * D + cm * E;
    const float a   = Sft / Stt;
    const float s   = (kp * sqrtf(B) - km * sqrtf(A)) / sqrtf(Stt);

    const float F   = W - Sft * Sft / Stt;
    const float Tm  = cp * C + cm * B;
    const float Tp  = cp * A + cm * C;
    const float St  = kp * Tm - km * Tp;
    const float Gv  = kp * kp * B + km * km * A - 2.f * kp * km * C
                      - 2.f * s * St + s * s * Stt;
    const float Sf  = kp * E - km * D;
    const float H   = Sf - a * St - s * Sft + s * a * Stt;

    const float sw  = (2.0f / PI_F) * atan2f(F, Gv);
    const float Hsw = H * sw;

    g1 = 1.f - Hsw;
    al = a * (Hsw - mu) * cp - km;
    be = a * (Hsw - mu) * cm + kp;
}

// ---- R: rolling reduce over images [ia, ib), no block-level syncs ------------
__global__ void __launch_bounds__(TA) nebReduceC(
    const float4* __restrict__ pos4,
    const float4* __restrict__ frc4,
    int nvec, int ia, int ib, int nb)
{
    const int b    = blockIdx.x;
    const int t    = threadIdx.x;
    const int warp = t >> 5;
    const int lane = t & 31;

    int  idx[KPT];
    bool ok[KPT];
    float4 pCur[KPT], dp[KPT];
    const float4 z = make_float4(0.f, 0.f, 0.f, 0.f);

    #pragma unroll
    for (int k = 0; k < KPT; k++) {
        int j = b * TILEA + k * TA + t;
        idx[k] = j;
        ok[k]  = (j < nvec);
        pCur[k] = z; dp[k] = z;
        if (ok[k]) {
            float4 pm = pos4[(size_t)(ia - 1) * nvec + j];
            pCur[k]   = pos4[(size_t)ia * nvec + j];
            dp[k].x = pCur[k].x - pm.x; dp[k].y = pCur[k].y - pm.y;
            dp[k].z = pCur[k].z - pm.z; dp[k].w = pCur[k].w - pm.w;
        }
    }

    for (int i = ia; i < ib; i++) {
        const int ii = i - 1;
        float vA = 0.f, vB = 0.f, vC = 0.f, vD = 0.f, vE = 0.f, vW = 0.f;

        #pragma unroll
        for (int k = 0; k < KPT; k++) {
            if (ok[k]) {
                float4 pN = pos4[(size_t)(i + 1) * nvec + idx[k]];
                float4 f  = frc4[(size_t)i * nvec + idx[k]];

                float dmx = pN.x - pCur[k].x, dmy = pN.y - pCur[k].y;
                float dmz = pN.z - pCur[k].z, dmw = pN.w - pCur[k].w;

                vA = fmaf(dp[k].x, dp[k].x, fmaf(dp[k].y, dp[k].y, fmaf(dp[k].z, dp[k].z, fmaf(dp[k].w, dp[k].w, vA))));
                vB = fmaf(dmx, dmx, fmaf(dmy, dmy, fmaf(dmz, dmz, fmaf(dmw, dmw, vB))));
                vC = fmaf(dp[k].x, dmx, fmaf(dp[k].y, dmy, fmaf(dp[k].z, dmz, fmaf(dp[k].w, dmw, vC))));
                vD = fmaf(f.x, dp[k].x, fmaf(f.y, dp[k].y, fmaf(f.z, dp[k].z, fmaf(f.w, dp[k].w, vD))));
                vE = fmaf(f.x, dmx, fmaf(f.y, dmy, fmaf(f.z, dmz, fmaf(f.w, dmw, vE))));
                vW = fmaf(f.x, f.x, fmaf(f.y, f.y, fmaf(f.z, f.z, fmaf(f.w, f.w, vW))));

                dp[k].x = dmx; dp[k].y = dmy; dp[k].z = dmz; dp[k].w = dmw;
                pCur[k] = pN;
            }
        }

        // warp-level reduce only; per-warp partial straight to global
        float vals[6] = { vA, vB, vC, vD, vE, vW };
        #pragma unroll
        for (int c = 0; c < 6; c++) vals[c] = warpSum(vals[c]);
        if (lane == 0) {
            float* pp = &g_part[(((size_t)ii * nb + b) * NW + warp) * 6];
            #pragma unroll
            for (int c = 0; c < 6; c++) pp[c] = vals[c];
        }
    }
}

// ---- S: fold per-warp partials -> coefficients for images [ia, ib) -----------
__global__ void nebScalarsC(int ia, int nb)
{
    const int ii = (ia - 1) + blockIdx.x;
    const int t  = threadIdx.x;          // 256
    const int total = nb * NW;

    float acc[6] = {0.f, 0.f, 0.f, 0.f, 0.f, 0.f};
    for (int p = t; p < total; p += 256) {
        const float* pp = &g_part[((size_t)ii * nb * NW + p) * 6];
        #pragma unroll
        for (int c = 0; c < 6; c++) acc[c] += pp[c];
    }

    __shared__ float sred[6][8];
    #pragma unroll
    for (int c = 0; c < 6; c++) {
        float r = warpSum(acc[c]);
        if ((t & 31) == 0) sred[c][t >> 5] = r;
    }
    __syncthreads();

    if (t == 0) {
        float S[6];
        #pragma unroll
        for (int c = 0; c < 6; c++) {
            float s = 0.f;
            #pragma unroll
            for (int w = 0; w < 8; w++) s += sred[c][w];
            S[c] = s;
        }
        float g1, al, be;
        coefFrom(S, ii, g1, al, be);
        g_coef[ii * 4 + 0] = g1;
        g_coef[ii * 4 + 1] = al;
        g_coef[ii * 4 + 2] = be;
    }
}

// ---- O: rolling output over images [ia, ib); pos/frc reads hit L2 ------------
__global__ void __launch_bounds__(TA) nebOutC(
    const float4* __restrict__ pos4,
    const float4* __restrict__ frc4,
    float4* __restrict__ out4,
    int nvec, int n_img, int ia, int ib,
    int copyFirst, int copyLast)
{
    const int b = blockIdx.x;
    const int t = threadIdx.x;

    int  idx[KPT];
    bool ok[KPT];
    #pragma unroll
    for (int k = 0; k < KPT; k++) {
        idx[k] = b * TILEA + k * TA + t;
        ok[k]  = (idx[k] < nvec);
    }

    if (copyFirst) {
        #pragma unroll
        for (int k = 0; k < KPT; k++) {
            if (ok[k]) {
                float4 f0 = __ldcs(&frc4[idx[k]]);
                __stcs(&out4[idx[k]], f0);
            }
        }
    }

    if (ia < ib) {
        float4 pCur[KPT], dp[KPT];
        const float4 z = make_float4(0.f, 0.f, 0.f, 0.f);
        #pragma unroll
        for (int k = 0; k < KPT; k++) {
            pCur[k] = z; dp[k] = z;
            if (ok[k]) {
                float4 pm = pos4[(size_t)(ia - 1) * nvec + idx[k]];
                pCur[k]   = pos4[(size_t)ia * nvec + idx[k]];
                dp[k].x = pCur[k].x - pm.x; dp[k].y = pCur[k].y - pm.y;
                dp[k].z = pCur[k].z - pm.z; dp[k].w = pCur[k].w - pm.w;
            }
        }

        for (int i = ia; i < ib; i++) {
            const int ii = i - 1;
            const float g1 = __ldg(&g_coef[ii * 4 + 0]);
            const float al = __ldg(&g_coef[ii * 4 + 1]);
            const float be = __ldg(&g_coef[ii * 4 + 2]);

            #pragma unroll
            for (int k = 0; k < KPT; k++) {
                if (ok[k]) {
                    float4 pN = pos4[(size_t)(i + 1) * nvec + idx[k]];
                    float4 f  = frc4[(size_t)i * nvec + idx[k]];

                    float dmx = pN.x - pCur[k].x, dmy = pN.y - pCur[k].y;
                    float dmz = pN.z - pCur[k].z, dmw = pN.w - pCur[k].w;

                    float4 o;
                    o.x = fmaf(g1, f.x, fmaf(al, dp[k].x, be * dmx));
                    o.y = fmaf(g1, f.y, fmaf(al, dp[k].y, be * dmy));
                    o.z = fmaf(g1, f.z, fmaf(al, dp[k].z, be * dmz));
                    o.w = fmaf(g1, f.w, fmaf(al, dp[k].w, be * dmw));
                    __stcs(&out4[(size_t)i * nvec + idx[k]], o);

                    dp[k].x = dmx; dp[k].y = dmy; dp[k].z = dmz; dp[k].w = dmw;
                    pCur[k] = pN;
                }
            }
        }
    }

    if (copyLast) {
        #pragma unroll
        for (int k = 0; k < KPT; k++) {
            if (ok[k]) {
                size_t g = (size_t)(n_img - 1) * nvec + idx[k];
                float4 fl = __ldcs(&frc4[g]);
                __stcs(&out4[g], fl);
            }
        }
    }
}

// =============================================================================
extern "C" void kernel_launch(void* const* d_in, const int* in_sizes, int n_in,
                              void* d_out, int out_size)
{
    const float* pos = (const float*)d_in[0];
    const float* frc = (const float*)d_in[1];
    const float* eng = (const float*)d_in[2];

    const int n_img    = in_sizes[2];                 // 32
    const long per_img = (long)in_sizes[0] / n_img;   // 1,200,000 floats
    const int  nvec    = (int)(per_img / 4);          // 300,000 float4
    const int  n_int   = n_img - 2;

    const float4* pos4 = (const float4*)pos;
    const float4* frc4 = (const float4*)frc;
    float4* out4 = (float4*)d_out;

    const int nb = (nvec + TILEA - 1) / TILEA;        // 586 blocks

    if (n_int < 1) {
        // no interior images: out = frc (both edges)
        nebOutC<<<nb, TA>>>(pos4, frc4, out4, nvec, n_img, 1, 1,
                            1, (n_img > 1) ? 1 : 0);
        return;
    }

    nebInit<<<1, 32>>>(eng, n_img);

    // chunk interior images [1, n_img-1) into CHUNK-sized pieces
    const int lastI = n_img - 1;                      // exclusive end (31)
    int nChunks = (n_int + CHUNK - 1) / CHUNK;
    int base = n_int / nChunks;                       // balanced chunk sizes
    int rem  = n_int % nChunks;

    int ia = 1;
    for (int c = 0; c < nChunks; c++) {
        int len = base + (c < rem ? 1 : 0);
        int ib  = ia + len;
        if (ib > lastI) ib = lastI;

        nebReduceC<<<nb, TA>>>(pos4, frc4, nvec, ia, ib, nb);
        nebScalarsC<<<(ib - ia), 256>>>(ia, nb);
        nebOutC<<<nb, TA>>>(pos4, frc4, out4, nvec, n_img, ia, ib,
                            (c == 0) ? 1 : 0,
                            (c == nChunks - 1) ? 1 : 0);
        ia = ib;
    }
}